// round 4
// baseline (speedup 1.0000x reference)
#include <cuda_runtime.h>

// Problem constants
// B=32, L=96, S=96, D=512, H=8, DH=64, H*DH=512, S*S=9216, B*L=3072
#define NB 32
#define NL 96
#define NS 96
#define ND 512
#define NHD 512          // H*DH
#define NSS 9216         // S*S
#define NROWS 3072       // B*L

// ---------------- scratch (static device globals; no allocation) -------------
__device__ __align__(16) float g_AQ[NB * NL * NHD];     // [b][i][nr]  (core-scaled q / H)
__device__ __align__(16) float g_K [NB * NHD * NS];     // [b][nr][j]
__device__ __align__(16) float g_V [NB * NHD * NS];     // [b][nr][k]
__device__ __align__(16) float g_full[NROWS * NSS];     // [b*96+i][j*96+k]  (113 MB)

// ---------------- packed f32x2 helpers (Blackwell FFMA2) ---------------------
typedef unsigned long long u64;

__device__ __forceinline__ void fma2(u64 &d, u64 a, u64 b) {
    // d = a*b + d, elementwise on packed {f32,f32}; exact fp32 rn semantics
    asm("fma.rn.f32x2 %0, %1, %2, %0;" : "+l"(d) : "l"(a), "l"(b));
}
__device__ __forceinline__ u64 lds2(const float* p) {
    return *reinterpret_cast<const u64*>(p);   // 8B-aligned LDS.64
}
__device__ __forceinline__ float2 unpack2(u64 v) {
    float2 r;
    r.x = __uint_as_float((unsigned int)(v & 0xffffffffull));
    r.y = __uint_as_float((unsigned int)(v >> 32));
    return r;
}

// =============================================================================
// Kernel 1: projection GEMM  Y = X(3072x512) @ W(512x512) + bias, with the
// raw-reshape scatter epilogue. mode: 0 -> AQ (scaled by core/H), 1 -> K, 2 -> V
// Tile 64x64, BK=16, 256 threads, packed 4x(2x2) microtile via FFMA2.
// =============================================================================
__global__ void __launch_bounds__(256) proj_kernel(
    const float* __restrict__ X, const float* __restrict__ W,
    const float* __restrict__ bias, const float* __restrict__ core, int mode)
{
    __shared__ float sAd[16][130];   // A rows duplicated: sAd[k][2m]=sAd[k][2m+1]=A[m][k]
    __shared__ float sBt[16][64];

    const int tid = threadIdx.x;
    const int tx = tid & 15, ty = tid >> 4;
    const int row0 = blockIdx.x * 64;
    const int col0 = blockIdx.y * 64;

    u64 acc[4][2];
    #pragma unroll
    for (int u = 0; u < 4; u++)
        #pragma unroll
        for (int w = 0; w < 2; w++) acc[u][w] = 0ull;

    const int m  = tid >> 2;
    const int kq = (tid & 3) * 4;
    const int kb = tid >> 4;
    const int nb = (tid & 15) * 4;
    const float* Xp = X + (row0 + m) * ND + kq;

    for (int k0 = 0; k0 < ND; k0 += 16) {
        float4 av = *reinterpret_cast<const float4*>(Xp + k0);
        *reinterpret_cast<float2*>(&sAd[kq + 0][2 * m]) = make_float2(av.x, av.x);
        *reinterpret_cast<float2*>(&sAd[kq + 1][2 * m]) = make_float2(av.y, av.y);
        *reinterpret_cast<float2*>(&sAd[kq + 2][2 * m]) = make_float2(av.z, av.z);
        *reinterpret_cast<float2*>(&sAd[kq + 3][2 * m]) = make_float2(av.w, av.w);
        *reinterpret_cast<float4*>(&sBt[kb][nb]) =
            *reinterpret_cast<const float4*>(&W[(k0 + kb) * ND + col0 + nb]);
        __syncthreads();

        #pragma unroll
        for (int kk = 0; kk < 16; kk++) {
            u64 a2[4], b2[2];
            #pragma unroll
            for (int u = 0; u < 4; u++) a2[u] = lds2(&sAd[kk][2 * (ty + 16 * u)]);
            #pragma unroll
            for (int w = 0; w < 2; w++) b2[w] = lds2(&sBt[kk][tx * 4 + 2 * w]);
            #pragma unroll
            for (int u = 0; u < 4; u++)
                #pragma unroll
                for (int w = 0; w < 2; w++) fma2(acc[u][w], a2[u], b2[w]);
        }
        __syncthreads();
    }

    // Scatter epilogue implementing (B,L,512) -> (H,B,L,64) raw reshape:
    // flat F = r*512+c = ((n*32+b)*96+i)*64+d
    #pragma unroll
    for (int u = 0; u < 4; u++) {
        int r  = row0 + ty + 16 * u;
        int nh = r / 384;
        int rem = r - nh * 384;
        int bb = rem / 12;
        int t8 = rem - bb * 12;
        #pragma unroll
        for (int w = 0; w < 2; w++) {
            float2 pv = unpack2(acc[u][w]);
            #pragma unroll
            for (int q = 0; q < 2; q++) {
                int   c   = col0 + tx * 4 + 2 * w + q;
                float val = (q ? pv.y : pv.x) + bias[c];
                int ii = t8 * 8 + (c >> 6);
                int dd = c & 63;
                int nr = nh * 64 + dd;
                if (mode == 0)
                    g_AQ[(bb * NL + ii) * NHD + nr] = val * core[nr] * 0.125f;
                else if (mode == 1)
                    g_K[(bb * NHD + nr) * NS + ii] = val;
                else
                    g_V[(bb * NHD + nr) * NS + ii] = val;
            }
        }
    }
}

// =============================================================================
// Kernel 2: per-(b,i) rank-512 outer-product reduction
//   full[b,i,j,k] = sum_nr AQ[b,i,nr] * K[b,nr,j] * V[b,nr,k]
// One block per (i,b). 96x96 output, 256 threads, 6x(3x2) packed microtile.
// AQ scaling folded into the K smem tile (rows duplicated for FFMA2).
// =============================================================================
__global__ void __launch_bounds__(256) stageA_kernel()
{
    __shared__ float sKd[32][192];   // K*AQ, each value duplicated: [c][2j],[2j+1]
    __shared__ float sVv[32][96];
    __shared__ float sAq[32];

    const int i = blockIdx.x;
    const int b = blockIdx.y;
    const int tid = threadIdx.x;
    const int tx = tid & 15, ty = tid >> 4;

    u64 acc[6][3];
    #pragma unroll
    for (int u = 0; u < 6; u++)
        #pragma unroll
        for (int w = 0; w < 3; w++) acc[u][w] = 0ull;

    const float* Kb = g_K + b * (NHD * NS);
    const float* Vb = g_V + b * (NHD * NS);
    const float* Aq = g_AQ + (b * NL + i) * NHD;

    for (int h0 = 0; h0 < NHD; h0 += 32) {
        if (tid < 32) sAq[tid] = Aq[h0 + tid];
        __syncthreads();
        #pragma unroll
        for (int t = 0; t < 12; t++) {
            int e = tid + t * 256;        // 0..3071 over the 32x96 chunk
            int c = e / 96;
            int j = e - c * 96;
            float kv = Kb[h0 * 96 + e] * sAq[c];
            *reinterpret_cast<float2*>(&sKd[c][2 * j]) = make_float2(kv, kv);
            sVv[c][j] = Vb[h0 * 96 + e];
        }
        __syncthreads();

        #pragma unroll 8
        for (int c = 0; c < 32; c++) {
            u64 a2[6], v2[3];
            #pragma unroll
            for (int u = 0; u < 6; u++) a2[u] = lds2(&sKd[c][2 * (ty * 6 + u)]);
            #pragma unroll
            for (int w = 0; w < 3; w++) v2[w] = lds2(&sVv[c][tx * 6 + 2 * w]);
            #pragma unroll
            for (int u = 0; u < 6; u++)
                #pragma unroll
                for (int w = 0; w < 3; w++) fma2(acc[u][w], a2[u], v2[w]);
        }
        __syncthreads();
    }

    float* out = g_full + (size_t)(b * NL + i) * NSS;
    #pragma unroll
    for (int u = 0; u < 6; u++) {
        int j = ty * 6 + u;
        #pragma unroll
        for (int w = 0; w < 3; w++) {
            float2 r = unpack2(acc[u][w]);
            out[j * 96 + tx * 6 + 2 * w]     = r.x;
            out[j * 96 + tx * 6 + 2 * w + 1] = r.y;
        }
    }
}

// =============================================================================
// Kernel 3: output GEMM  out(3072x512) = full(3072x9216) @ Wo(9216x512) + bo
// Tile 64x64, BK=16, 256 threads, packed FFMA2 (A rows duplicated).
// =============================================================================
__global__ void __launch_bounds__(256) stageB_kernel(
    const float* __restrict__ Wo, const float* __restrict__ bo,
    float* __restrict__ out)
{
    __shared__ float sAd[16][130];
    __shared__ float sBt[16][64];

    const int tid = threadIdx.x;
    const int tx = tid & 15, ty = tid >> 4;
    const int row0 = blockIdx.x * 64;
    const int col0 = blockIdx.y * 64;

    u64 acc[4][2];
    #pragma unroll
    for (int u = 0; u < 4; u++)
        #pragma unroll
        for (int w = 0; w < 2; w++) acc[u][w] = 0ull;

    const int m  = tid >> 2;
    const int kq = (tid & 3) * 4;
    const int kb = tid >> 4;
    const int nb = (tid & 15) * 4;
    const float* Fp = g_full + (size_t)(row0 + m) * NSS + kq;

    for (int k0 = 0; k0 < NSS; k0 += 16) {
        float4 av = *reinterpret_cast<const float4*>(Fp + k0);
        *reinterpret_cast<float2*>(&sAd[kq + 0][2 * m]) = make_float2(av.x, av.x);
        *reinterpret_cast<float2*>(&sAd[kq + 1][2 * m]) = make_float2(av.y, av.y);
        *reinterpret_cast<float2*>(&sAd[kq + 2][2 * m]) = make_float2(av.z, av.z);
        *reinterpret_cast<float2*>(&sAd[kq + 3][2 * m]) = make_float2(av.w, av.w);
        *reinterpret_cast<float4*>(&sBt[kb][nb]) =
            *reinterpret_cast<const float4*>(&Wo[(k0 + kb) * ND + col0 + nb]);
        __syncthreads();

        #pragma unroll
        for (int kk = 0; kk < 16; kk++) {
            u64 a2[4], b2[2];
            #pragma unroll
            for (int u = 0; u < 4; u++) a2[u] = lds2(&sAd[kk][2 * (ty + 16 * u)]);
            #pragma unroll
            for (int w = 0; w < 2; w++) b2[w] = lds2(&sBt[kk][tx * 4 + 2 * w]);
            #pragma unroll
            for (int u = 0; u < 4; u++)
                #pragma unroll
                for (int w = 0; w < 2; w++) fma2(acc[u][w], a2[u], b2[w]);
        }
        __syncthreads();
    }

    #pragma unroll
    for (int u = 0; u < 4; u++) {
        int r = row0 + ty + 16 * u;
        #pragma unroll
        for (int w = 0; w < 2; w++) {
            float2 t = unpack2(acc[u][w]);
            int c = col0 + tx * 4 + 2 * w;
            out[r * ND + c]     = t.x + bo[c];
            out[r * ND + c + 1] = t.y + bo[c + 1];
        }
    }
}

// =============================================================================
// Launch: 3 projection GEMMs -> stage A (full) -> stage B (output GEMM)
// All on the default stream (graph-capturable, no sync, no allocation).
// =============================================================================
extern "C" void kernel_launch(void* const* d_in, const int* in_sizes, int n_in,
                              void* d_out, int out_size)
{
    (void)in_sizes; (void)n_in; (void)out_size;
    const float* queries = (const float*)d_in[0];
    const float* keys    = (const float*)d_in[1];
    const float* values  = (const float*)d_in[2];
    // d_in[3] = attn_mask (all false; unused by the reference math)
    const float* Wq = (const float*)d_in[4];
    const float* bq = (const float*)d_in[5];
    const float* Wk = (const float*)d_in[6];
    const float* bk = (const float*)d_in[7];
    const float* Wv = (const float*)d_in[8];
    const float* bv = (const float*)d_in[9];
    const float* core = (const float*)d_in[10];
    const float* Wo = (const float*)d_in[11];
    const float* bo = (const float*)d_in[12];
    float* out = (float*)d_out;

    dim3 gp(NROWS / 64, ND / 64);          // 48 x 8
    proj_kernel<<<gp, 256>>>(queries, Wq, bq, core, 0);
    proj_kernel<<<gp, 256>>>(keys,    Wk, bk, core, 1);
    proj_kernel<<<gp, 256>>>(values,  Wv, bv, core, 2);

    stageA_kernel<<<dim3(NL, NB), 256>>>();          // 96 x 32 blocks

    stageB_kernel<<<dim3(NROWS / 64, ND / 64), 256>>>(Wo, bo, out);
}

// round 5
// speedup vs baseline: 1.8962x; 1.8962x over previous
#include <cuda_runtime.h>

// B=32, L=96, S=96, D=512, H=8, DH=64, H*DH=512, S*S=9216, B*L=3072
#define NB 32
#define NL 96
#define NS 96
#define ND 512
#define NHD 512
#define NSS 9216
#define NROWS 3072

// ---------------- scratch (static device globals; no allocation) -------------
__device__ __align__(16) float g_AQ[NB * NL * NHD];        // [b][i][r]  (core*q/H)
__device__ __align__(16) float g_K [NB * NS * NHD];        // [b][j][r]  r contiguous
__device__ __align__(16) float g_V [NB * NS * NHD];        // [b][k][r]  r contiguous
__device__ __align__(16) float g_full[(size_t)NROWS * NSS];// [b*96+i][j*96+k] 113MB
__device__ __align__(16) float g_part[3][NROWS * ND];      // split-K partials 19MB

// ---------------- packed f32x2 helpers ---------------------------------------
typedef unsigned long long u64;

__device__ __forceinline__ void fma2(u64 &d, u64 a, u64 b) {
    asm("fma.rn.f32x2 %0, %1, %2, %0;" : "+l"(d) : "l"(a), "l"(b));
}
__device__ __forceinline__ u64 mul2(u64 a, u64 b) {
    u64 d; asm("mul.rn.f32x2 %0, %1, %2;" : "=l"(d) : "l"(a), "l"(b)); return d;
}
__device__ __forceinline__ u64 lds2(const float* p) {
    return *reinterpret_cast<const u64*>(p);
}
__device__ __forceinline__ float hsum2(u64 v) {
    float lo = __uint_as_float((unsigned)(v & 0xffffffffull));
    float hi = __uint_as_float((unsigned)(v >> 32));
    return lo + hi;
}

// =============================================================================
// Kernel 1: fused projections. grid (24, 8, 3), 128x64 tile, k-pair packing.
// z=0: AQ (scaled core/H), z=1: K, z=2: V. Raw-reshape scatter epilogue.
// =============================================================================
__global__ void __launch_bounds__(256) proj_kernel(
    const float* __restrict__ Xq, const float* __restrict__ Xk, const float* __restrict__ Xv,
    const float* __restrict__ Wq, const float* __restrict__ Wk, const float* __restrict__ Wv,
    const float* __restrict__ bq, const float* __restrict__ bk, const float* __restrict__ bv,
    const float* __restrict__ core)
{
    __shared__ float sX[128][34];   // rows k-major (pairs contiguous)
    __shared__ float sW[64][34];    // W transposed: [col][k]

    const int mode = blockIdx.z;
    const float* X    = mode == 0 ? Xq : (mode == 1 ? Xk : Xv);
    const float* W    = mode == 0 ? Wq : (mode == 1 ? Wk : Wv);
    const float* bias = mode == 0 ? bq : (mode == 1 ? bk : bv);

    const int tid = threadIdx.x;
    const int tx = tid & 15, ty = tid >> 4;
    const int row0 = blockIdx.x * 128;
    const int col0 = blockIdx.y * 64;

    u64 acc[8][4];
    #pragma unroll
    for (int u = 0; u < 8; u++)
        #pragma unroll
        for (int w = 0; w < 4; w++) acc[u][w] = 0ull;

    for (int k0 = 0; k0 < ND; k0 += 32) {
        #pragma unroll
        for (int t = 0; t < 8; t++) {                 // 2048 float2 X fill
            int e2 = tid + t * 256;
            int row = e2 >> 4, c2 = e2 & 15;
            *reinterpret_cast<float2*>(&sX[row][c2 * 2]) =
                *reinterpret_cast<const float2*>(&X[(row0 + row) * ND + k0 + c2 * 2]);
        }
        #pragma unroll
        for (int t = 0; t < 2; t++) {                 // 512 float4 W fill (transpose)
            int idx = tid + t * 256;
            int kk = idx >> 4, c4 = idx & 15;
            float4 wv = *reinterpret_cast<const float4*>(&W[(k0 + kk) * ND + col0 + c4 * 4]);
            sW[c4 * 4 + 0][kk] = wv.x;
            sW[c4 * 4 + 1][kk] = wv.y;
            sW[c4 * 4 + 2][kk] = wv.z;
            sW[c4 * 4 + 3][kk] = wv.w;
        }
        __syncthreads();

        #pragma unroll 2
        for (int kp = 0; kp < 16; kp++) {
            u64 a2[8], b2[4];
            #pragma unroll
            for (int u = 0; u < 8; u++) a2[u] = lds2(&sX[ty * 8 + u][2 * kp]);
            #pragma unroll
            for (int w = 0; w < 4; w++) b2[w] = lds2(&sW[tx + 16 * w][2 * kp]);
            #pragma unroll
            for (int u = 0; u < 8; u++)
                #pragma unroll
                for (int w = 0; w < 4; w++) fma2(acc[u][w], a2[u], b2[w]);
        }
        __syncthreads();
    }

    // reshape scatter: F = r*512+c = ((n*32+b)*96+i)*64+d
    #pragma unroll
    for (int u = 0; u < 8; u++) {
        int r  = row0 + ty * 8 + u;
        int nh = r / 384;
        int rem = r - nh * 384;
        int bb = rem / 12;
        int t8 = rem - bb * 12;
        #pragma unroll
        for (int w = 0; w < 4; w++) {
            int c = col0 + tx + 16 * w;
            float val = hsum2(acc[u][w]) + bias[c];
            int ii = t8 * 8 + (c >> 6);
            int dd = c & 63;
            int nr = nh * 64 + dd;
            if (mode == 0)
                g_AQ[(bb * NL + ii) * NHD + nr] = val * core[nr] * 0.125f;
            else if (mode == 1)
                g_K[(bb * NS + ii) * NHD + nr] = val;
            else
                g_V[(bb * NS + ii) * NHD + nr] = val;
        }
    }
}

// =============================================================================
// Kernel 2: full[b,i,j,k] = sum_r AQ[b,i,r]*K[b,j,r]*V[b,k,r]
// One block per (i-pair, b): two 96x96 outputs. r-pair packing, no duplication.
// Thread microtile: 2(i) x 6(j) x 6(k) packed partial pairs.
// =============================================================================
__global__ void __launch_bounds__(256) stageA_kernel()
{
    __shared__ float sK[96][34];    // [j][r] r-pairs contiguous, stride 34 (conflict-free)
    __shared__ float sV[96][34];    // [k][r]
    __shared__ float sAq[2][32];

    const int tid = threadIdx.x;
    const int tx = tid & 15, ty = tid >> 4;
    const int i0 = blockIdx.x * 2;
    const int b  = blockIdx.y;

    const float* Kb = g_K + b * (NS * NHD);
    const float* Vb = g_V + b * (NS * NHD);
    const float* Aq = g_AQ + (b * NL + i0) * NHD;

    u64 acc0[6][6], acc1[6][6];
    #pragma unroll
    for (int u = 0; u < 6; u++)
        #pragma unroll
        for (int w = 0; w < 6; w++) { acc0[u][w] = 0ull; acc1[u][w] = 0ull; }

    for (int r0 = 0; r0 < NHD; r0 += 32) {
        if (tid < 64)
            sAq[tid >> 5][tid & 31] = Aq[(tid >> 5) * NHD + r0 + (tid & 31)];
        #pragma unroll
        for (int t = 0; t < 6; t++) {                 // 1536 float2 per array
            int e2 = tid + t * 256;
            int row = e2 >> 4, c2 = e2 & 15;
            *reinterpret_cast<float2*>(&sK[row][c2 * 2]) =
                *reinterpret_cast<const float2*>(&Kb[row * NHD + r0 + c2 * 2]);
            *reinterpret_cast<float2*>(&sV[row][c2 * 2]) =
                *reinterpret_cast<const float2*>(&Vb[row * NHD + r0 + c2 * 2]);
        }
        __syncthreads();

        #pragma unroll 2
        for (int rp = 0; rp < 16; rp++) {
            u64 q0 = lds2(&sAq[0][2 * rp]);
            u64 q1 = lds2(&sAq[1][2 * rp]);
            u64 a2[6], v2[6];
            #pragma unroll
            for (int u = 0; u < 6; u++) a2[u] = lds2(&sK[ty * 6 + u][2 * rp]);
            #pragma unroll
            for (int w = 0; w < 6; w++) v2[w] = lds2(&sV[tx + 16 * w][2 * rp]);
            #pragma unroll
            for (int u = 0; u < 6; u++) {
                u64 t0 = mul2(a2[u], q0);
                u64 t1 = mul2(a2[u], q1);
                #pragma unroll
                for (int w = 0; w < 6; w++) {
                    fma2(acc0[u][w], t0, v2[w]);
                    fma2(acc1[u][w], t1, v2[w]);
                }
            }
        }
        __syncthreads();
    }

    float* o0 = g_full + (size_t)(b * NL + i0) * NSS;
    #pragma unroll
    for (int u = 0; u < 6; u++) {
        int j = ty * 6 + u;
        #pragma unroll
        for (int w = 0; w < 6; w++) {
            int k = tx + 16 * w;
            o0[j * 96 + k]       = hsum2(acc0[u][w]);
            o0[NSS + j * 96 + k] = hsum2(acc1[u][w]);
        }
    }
}

// =============================================================================
// Kernel 3: out_partial = full(3072x9216) @ Wo(9216x512), split-K=3.
// 128x128 tile, k-pair packing both operands (no duplication), U=W=8.
// grid (24, 4, 3) = 288 blocks (~2 full waves on 148 SMs).
// =============================================================================
__global__ void __launch_bounds__(256) stageB_kernel(const float* __restrict__ Wo)
{
    __shared__ float sA[128][34];   // full rows, k-major
    __shared__ float sB[128][34];   // Wo transposed: [col][k]

    const int tid = threadIdx.x;
    const int tx = tid & 15, ty = tid >> 4;
    const int row0  = blockIdx.x * 128;
    const int col0  = blockIdx.y * 128;
    const int kbase = blockIdx.z * 3072;

    u64 acc[8][8];
    #pragma unroll
    for (int u = 0; u < 8; u++)
        #pragma unroll
        for (int w = 0; w < 8; w++) acc[u][w] = 0ull;

    for (int k0 = 0; k0 < 3072; k0 += 32) {
        #pragma unroll
        for (int t = 0; t < 8; t++) {                 // 2048 float2 A fill
            int e2 = tid + t * 256;
            int row = e2 >> 4, c2 = e2 & 15;
            *reinterpret_cast<float2*>(&sA[row][c2 * 2]) =
                *reinterpret_cast<const float2*>(
                    &g_full[(size_t)(row0 + row) * NSS + kbase + k0 + c2 * 2]);
        }
        #pragma unroll
        for (int t = 0; t < 4; t++) {                 // 1024 float4 Wo fill (transpose)
            int idx = tid + t * 256;
            int kk = idx >> 5, c4 = idx & 31;
            float4 wv = *reinterpret_cast<const float4*>(
                &Wo[(size_t)(kbase + k0 + kk) * ND + col0 + c4 * 4]);
            sB[c4 * 4 + 0][kk] = wv.x;
            sB[c4 * 4 + 1][kk] = wv.y;
            sB[c4 * 4 + 2][kk] = wv.z;
            sB[c4 * 4 + 3][kk] = wv.w;
        }
        __syncthreads();

        #pragma unroll 2
        for (int kp = 0; kp < 16; kp++) {
            u64 a2[8], b2[8];
            #pragma unroll
            for (int u = 0; u < 8; u++) a2[u] = lds2(&sA[ty * 8 + u][2 * kp]);
            #pragma unroll
            for (int w = 0; w < 8; w++) b2[w] = lds2(&sB[tx + 16 * w][2 * kp]);
            #pragma unroll
            for (int u = 0; u < 8; u++)
                #pragma unroll
                for (int w = 0; w < 8; w++) fma2(acc[u][w], a2[u], b2[w]);
        }
        __syncthreads();
    }

    float* part = g_part[blockIdx.z];
    #pragma unroll
    for (int u = 0; u < 8; u++) {
        int r = row0 + ty * 8 + u;
        #pragma unroll
        for (int w = 0; w < 8; w++)
            part[r * ND + col0 + tx + 16 * w] = hsum2(acc[u][w]);
    }
}

// =============================================================================
// Kernel 4: out = p0 + p1 + p2 + bias (float4 vectorized)
// =============================================================================
__global__ void __launch_bounds__(256) reduce_kernel(
    const float* __restrict__ bo, float* __restrict__ out)
{
    int idx = blockIdx.x * 256 + threadIdx.x;          // float4 index, 393216 total
    float4 a = reinterpret_cast<const float4*>(g_part[0])[idx];
    float4 b = reinterpret_cast<const float4*>(g_part[1])[idx];
    float4 c = reinterpret_cast<const float4*>(g_part[2])[idx];
    float4 bb = reinterpret_cast<const float4*>(bo)[idx & 127];  // 512 floats = 128 float4/row
    float4 r;
    r.x = a.x + b.x + c.x + bb.x;
    r.y = a.y + b.y + c.y + bb.y;
    r.z = a.z + b.z + c.z + bb.z;
    r.w = a.w + b.w + c.w + bb.w;
    reinterpret_cast<float4*>(out)[idx] = r;
}

// =============================================================================
extern "C" void kernel_launch(void* const* d_in, const int* in_sizes, int n_in,
                              void* d_out, int out_size)
{
    (void)in_sizes; (void)n_in; (void)out_size;
    const float* queries = (const float*)d_in[0];
    const float* keys    = (const float*)d_in[1];
    const float* values  = (const float*)d_in[2];
    // d_in[3] = attn_mask (all false; no effect on the math)
    const float* Wq = (const float*)d_in[4];
    const float* bq = (const float*)d_in[5];
    const float* Wk = (const float*)d_in[6];
    const float* bk = (const float*)d_in[7];
    const float* Wv = (const float*)d_in[8];
    const float* bv = (const float*)d_in[9];
    const float* core = (const float*)d_in[10];
    const float* Wo = (const float*)d_in[11];
    const float* bo = (const float*)d_in[12];
    float* out = (float*)d_out;

    proj_kernel<<<dim3(24, 8, 3), 256>>>(queries, keys, values,
                                         Wq, Wk, Wv, bq, bk, bv, core);
    stageA_kernel<<<dim3(48, 32), 256>>>();
    stageB_kernel<<<dim3(24, 4, 3), 256>>>(Wo);
    reduce_kernel<<<1536, 256>>>(bo, out);
}

// round 7
// speedup vs baseline: 3.9223x; 2.0685x over previous
#include <cuda_runtime.h>
#include <cuda_bf16.h>
#include <cstdint>

// B=32, L=96, S=96, D=512, H=8, DH=64, H*DH=512, S*S=9216, B*L=3072
#define NB 32
#define NL 96
#define NS 96
#define ND 512
#define NHD 512
#define NSS 9216
#define NROWS 3072

// ---------------- scratch (static device globals; no allocation) -------------
__device__ __align__(16) float g_AQ[NB * NL * NHD];            // [b][i][r]
__device__ __align__(16) float g_K [NB * NS * NHD];            // [b][j][r]
__device__ __align__(16) float g_V [NB * NS * NHD];            // [b][k][r]
__device__ __align__(16) __nv_bfloat16 g_Vh[NB * NS * NHD];
__device__ __align__(16) __nv_bfloat16 g_Vl[NB * NS * NHD];
__device__ __align__(16) __nv_bfloat16 g_full_h[(size_t)NROWS * NSS];
__device__ __align__(16) __nv_bfloat16 g_full_l[(size_t)NROWS * NSS];
__device__ __align__(16) __nv_bfloat16 g_Woth[ND * NSS];       // Wo^T hi: [c][t]
__device__ __align__(16) __nv_bfloat16 g_Wotl[ND * NSS];       // Wo^T lo: [c][t]
__device__ __align__(16) float g_part[3][NROWS * ND];

// ---------------- helpers -----------------------------------------------------
__device__ __forceinline__ uint32_t smem_u32(const void* p) {
    uint32_t a;
    asm("{ .reg .u64 t; cvta.to.shared.u64 t, %1; cvt.u32.u64 %0, t; }"
        : "=r"(a) : "l"(p));
    return a;
}
__device__ __forceinline__ void ldsm_x4(uint32_t r[4], uint32_t addr) {
    asm volatile("ldmatrix.sync.aligned.m8n8.x4.shared.b16 {%0,%1,%2,%3}, [%4];"
        : "=r"(r[0]), "=r"(r[1]), "=r"(r[2]), "=r"(r[3]) : "r"(addr));
}
__device__ __forceinline__ void mma_bf16(float d[4], const uint32_t a[4],
                                         const uint32_t* b) {
    asm volatile(
        "mma.sync.aligned.m16n8k16.row.col.f32.bf16.bf16.f32 "
        "{%0,%1,%2,%3}, {%4,%5,%6,%7}, {%8,%9}, {%0,%1,%2,%3};"
        : "+f"(d[0]), "+f"(d[1]), "+f"(d[2]), "+f"(d[3])
        : "r"(a[0]), "r"(a[1]), "r"(a[2]), "r"(a[3]), "r"(b[0]), "r"(b[1]));
}
__device__ __forceinline__ uint32_t split2(float a, float b, uint32_t &lo_out) {
    __nv_bfloat16 ha = __float2bfloat16(a), hb = __float2bfloat16(b);
    __nv_bfloat16 la = __float2bfloat16(a - __bfloat162float(ha));
    __nv_bfloat16 lb = __float2bfloat16(b - __bfloat162float(hb));
    lo_out = (uint32_t)__bfloat16_as_ushort(la) | ((uint32_t)__bfloat16_as_ushort(lb) << 16);
    return (uint32_t)__bfloat16_as_ushort(ha) | ((uint32_t)__bfloat16_as_ushort(hb) << 16);
}

// ---------------- packed f32x2 (projections) ----------------------------------
typedef unsigned long long u64;
__device__ __forceinline__ void fma2(u64 &d, u64 a, u64 b) {
    asm("fma.rn.f32x2 %0, %1, %2, %0;" : "+l"(d) : "l"(a), "l"(b));
}
__device__ __forceinline__ u64 lds2(const float* p) { return *reinterpret_cast<const u64*>(p); }
__device__ __forceinline__ float hsum2(u64 v) {
    return __uint_as_float((unsigned)(v & 0xffffffffull)) + __uint_as_float((unsigned)(v >> 32));
}

// =============================================================================
// Kernel 1: fused projections (fp32 FFMA2) — R4-proven
// =============================================================================
__global__ void __launch_bounds__(256) proj_kernel(
    const float* __restrict__ Xq, const float* __restrict__ Xk, const float* __restrict__ Xv,
    const float* __restrict__ Wq, const float* __restrict__ Wk, const float* __restrict__ Wv,
    const float* __restrict__ bq, const float* __restrict__ bk, const float* __restrict__ bv,
    const float* __restrict__ core)
{
    __shared__ float sX[128][34];
    __shared__ float sW[64][34];

    const int mode = blockIdx.z;
    const float* X    = mode == 0 ? Xq : (mode == 1 ? Xk : Xv);
    const float* W    = mode == 0 ? Wq : (mode == 1 ? Wk : Wv);
    const float* bias = mode == 0 ? bq : (mode == 1 ? bk : bv);

    const int tid = threadIdx.x;
    const int tx = tid & 15, ty = tid >> 4;
    const int row0 = blockIdx.x * 128;
    const int col0 = blockIdx.y * 64;

    u64 acc[8][4];
    #pragma unroll
    for (int u = 0; u < 8; u++)
        #pragma unroll
        for (int w = 0; w < 4; w++) acc[u][w] = 0ull;

    for (int k0 = 0; k0 < ND; k0 += 32) {
        #pragma unroll
        for (int t = 0; t < 8; t++) {
            int e2 = tid + t * 256;
            int row = e2 >> 4, c2 = e2 & 15;
            *reinterpret_cast<float2*>(&sX[row][c2 * 2]) =
                *reinterpret_cast<const float2*>(&X[(row0 + row) * ND + k0 + c2 * 2]);
        }
        #pragma unroll
        for (int t = 0; t < 2; t++) {
            int idx = tid + t * 256;
            int kk = idx >> 4, c4 = idx & 15;
            float4 wv = *reinterpret_cast<const float4*>(&W[(k0 + kk) * ND + col0 + c4 * 4]);
            sW[c4 * 4 + 0][kk] = wv.x;
            sW[c4 * 4 + 1][kk] = wv.y;
            sW[c4 * 4 + 2][kk] = wv.z;
            sW[c4 * 4 + 3][kk] = wv.w;
        }
        __syncthreads();
        #pragma unroll 2
        for (int kp = 0; kp < 16; kp++) {
            u64 a2[8], b2[4];
            #pragma unroll
            for (int u = 0; u < 8; u++) a2[u] = lds2(&sX[ty * 8 + u][2 * kp]);
            #pragma unroll
            for (int w = 0; w < 4; w++) b2[w] = lds2(&sW[tx + 16 * w][2 * kp]);
            #pragma unroll
            for (int u = 0; u < 8; u++)
                #pragma unroll
                for (int w = 0; w < 4; w++) fma2(acc[u][w], a2[u], b2[w]);
        }
        __syncthreads();
    }

    #pragma unroll
    for (int u = 0; u < 8; u++) {
        int r  = row0 + ty * 8 + u;
        int nh = r / 384;
        int rem = r - nh * 384;
        int bb = rem / 12;
        int t8 = rem - bb * 12;
        #pragma unroll
        for (int w = 0; w < 4; w++) {
            int c = col0 + tx + 16 * w;
            float val = hsum2(acc[u][w]) + bias[c];
            int ii = t8 * 8 + (c >> 6);
            int dd = c & 63;
            int nr = nh * 64 + dd;
            if (mode == 0)
                g_AQ[(bb * NL + ii) * NHD + nr] = val * core[nr] * 0.125f;
            else if (mode == 1)
                g_K[(bb * NS + ii) * NHD + nr] = val;
            else
                g_V[(bb * NS + ii) * NHD + nr] = val;
        }
    }
}

// =============================================================================
// Kernel 2a: V fp32 -> split bf16
// =============================================================================
__global__ void __launch_bounds__(256) convV_kernel()
{
    int idx = blockIdx.x * 256 + threadIdx.x;
    float4 v = reinterpret_cast<const float4*>(g_V)[idx];
    uint32_t l0, l1;
    uint32_t h0 = split2(v.x, v.y, l0);
    uint32_t h1 = split2(v.z, v.w, l1);
    reinterpret_cast<uint2*>(g_Vh)[idx] = make_uint2(h0, h1);
    reinterpret_cast<uint2*>(g_Vl)[idx] = make_uint2(l0, l1);
}

// =============================================================================
// Kernel 2b: Wo[t][c] -> Wot[c][t] split bf16 (tiled transpose)
// =============================================================================
__global__ void __launch_bounds__(256) convWo_kernel(const float* __restrict__ Wo)
{
    __shared__ float tile[32][33];
    const int t0 = blockIdx.x * 32;
    const int c0 = blockIdx.y * 32;
    const int tx = threadIdx.x & 31, ty = threadIdx.x >> 5;
    #pragma unroll
    for (int s = 0; s < 4; s++)
        tile[ty + 8 * s][tx] = Wo[(size_t)(t0 + ty + 8 * s) * ND + c0 + tx];
    __syncthreads();
    #pragma unroll
    for (int s = 0; s < 4; s++) {
        float f = tile[tx][ty + 8 * s];
        __nv_bfloat16 h = __float2bfloat16(f);
        __nv_bfloat16 l = __float2bfloat16(f - __bfloat162float(h));
        size_t o = (size_t)(c0 + ty + 8 * s) * NSS + t0 + tx;
        g_Woth[o] = h;
        g_Wotl[o] = l;
    }
}

// =============================================================================
// Kernel 3: stage A via HMMA (mma.sync m16n8k16 bf16, 3-term split)
//   per b: full[m=i*96+j][k] = sum_r (AQ[i,r]*K[j,r]) * V[k,r]
//   grid (72, 32); block tile 128(m) x 96(n); K-chunk 32; 8 warps = 4m x 2n.
// =============================================================================
#define SA_STRIDE 40   // bf16 elems per row (32 + 8 pad) -> 80B, ldmatrix conflict-free
__global__ void __launch_bounds__(256) stageA_hmma()
{
    __shared__ __nv_bfloat16 sAh[128 * SA_STRIDE];
    __shared__ __nv_bfloat16 sAl[128 * SA_STRIDE];
    __shared__ __nv_bfloat16 sBh[96 * SA_STRIDE];
    __shared__ __nv_bfloat16 sBl[96 * SA_STRIDE];
    __shared__ float AQ_s[2 * 32];

    const int tid = threadIdx.x;
    const int wid = tid >> 5, lane = tid & 31;
    const int t = blockIdx.x;
    const int b = blockIdx.y;
    const int i0 = (t * 128) / 96;
    const int wm = (wid & 3) * 32;     // warp m origin in tile
    const int wn = (wid >> 2) * 48;    // warp n origin in tile

    const uint32_t uAh = smem_u32(sAh), uAl = smem_u32(sAl);
    const uint32_t uBh = smem_u32(sBh), uBl = smem_u32(sBl);

    const float* Kg  = g_K  + (size_t)(b * NS) * NHD;
    const float* AQg = g_AQ + (size_t)(b * NL) * NHD;
    const __nv_bfloat16* Vhg = g_Vh + (size_t)(b * NS) * NHD;
    const __nv_bfloat16* Vlg = g_Vl + (size_t)(b * NS) * NHD;

    float d[2][6][4];
    #pragma unroll
    for (int mf = 0; mf < 2; mf++)
        #pragma unroll
        for (int nf = 0; nf < 6; nf++)
            #pragma unroll
            for (int q = 0; q < 4; q++) d[mf][nf][q] = 0.0f;

    for (int ch = 0; ch < 16; ch++) {
        const int r0 = ch * 32;
        // AQ chunk (2 rows x 32)
        if (tid < 64)
            AQ_s[tid] = AQg[(size_t)(i0 + (tid >> 5)) * NHD + r0 + (tid & 31)];
        // V hi/lo -> sB (96 rows x 4 uint2)
        #pragma unroll
        for (int s = 0; s < 3; s++) {
            int item = tid + s * 256;            // 768 uint2
            int n = item >> 3, p4 = item & 7;
            uint2 vh = *reinterpret_cast<const uint2*>(&Vhg[(size_t)n * NHD + r0 + p4 * 4]);
            uint2 vl = *reinterpret_cast<const uint2*>(&Vlg[(size_t)n * NHD + r0 + p4 * 4]);
            *reinterpret_cast<uint2*>(&sBh[n * SA_STRIDE + p4 * 4]) = vh;
            *reinterpret_cast<uint2*>(&sBl[n * SA_STRIDE + p4 * 4]) = vl;
        }
        __syncthreads();   // AQ_s ready before build reads it
        // build A = AQ*K split (128 rows x 8 quads)
        #pragma unroll
        for (int s = 0; s < 4; s++) {
            int item = tid + s * 256;            // 1024 quads
            int mrow = item >> 3, p4 = item & 7;
            int m = t * 128 + mrow;
            int i = m / 96;
            int j = m - i * 96;
            int isel = i - i0;
            float4 kv = *reinterpret_cast<const float4*>(&Kg[(size_t)j * NHD + r0 + p4 * 4]);
            float4 qv = *reinterpret_cast<const float4*>(&AQ_s[isel * 32 + p4 * 4]);
            uint32_t lo0, lo1;
            uint32_t hi0 = split2(qv.x * kv.x, qv.y * kv.y, lo0);
            uint32_t hi1 = split2(qv.z * kv.z, qv.w * kv.w, lo1);
            *reinterpret_cast<uint2*>(&sAh[mrow * SA_STRIDE + p4 * 4]) = make_uint2(hi0, hi1);
            *reinterpret_cast<uint2*>(&sAl[mrow * SA_STRIDE + p4 * 4]) = make_uint2(lo0, lo1);
        }
        __syncthreads();

        #pragma unroll
        for (int ks = 0; ks < 2; ks++) {
            const int k = ks * 16;
            uint32_t ah[2][4], al[2][4], bh[3][4], bl[3][4];
            // A fragments: lanes 0-15 rows, lanes 16-31 k+8 half
            #pragma unroll
            for (int mf = 0; mf < 2; mf++) {
                uint32_t off = (uint32_t)((wm + mf * 16 + (lane & 15)) * SA_STRIDE
                                          + k + (lane >> 4) * 8) * 2;
                ldsm_x4(ah[mf], uAh + off);
                ldsm_x4(al[mf], uAl + off);
            }
            // B fragments (V rows = n): x4 covers two n8 frags
            #pragma unroll
            for (int nq = 0; nq < 3; nq++) {
                uint32_t off = (uint32_t)((wn + nq * 16 + (lane & 7) + ((lane >> 4) & 1) * 8)
                                          * SA_STRIDE + k + ((lane >> 3) & 1) * 8) * 2;
                ldsm_x4(bh[nq], uBh + off);
                ldsm_x4(bl[nq], uBl + off);
            }
            // 3 split terms, interleaved across 12 D frags
            #pragma unroll
            for (int t3 = 0; t3 < 3; t3++) {
                uint32_t (*A)[4]  = (t3 == 2) ? al : ah;
                uint32_t (*Bf)[4] = (t3 == 1) ? bl : bh;
                #pragma unroll
                for (int mf = 0; mf < 2; mf++)
                    #pragma unroll
                    for (int nq = 0; nq < 3; nq++) {
                        mma_bf16(d[mf][nq * 2 + 0], A[mf], &Bf[nq][0]);
                        mma_bf16(d[mf][nq * 2 + 1], A[mf], &Bf[nq][2]);
                    }
            }
        }
        __syncthreads();
    }

    // epilogue: split-bf16 store of D fragments into g_full
    const size_t base = (size_t)b * ((size_t)NL * NSS);
    #pragma unroll
    for (int mf = 0; mf < 2; mf++) {
        int m = t * 128 + wm + mf * 16 + (lane >> 2);
        #pragma unroll
        for (int nf = 0; nf < 6; nf++) {
            int c = wn + nf * 8 + (lane & 3) * 2;
            uint32_t lo, hi;
            hi = split2(d[mf][nf][0], d[mf][nf][1], lo);
            *reinterpret_cast<uint32_t*>(&g_full_h[base + (size_t)m * 96 + c]) = hi;
            *reinterpret_cast<uint32_t*>(&g_full_l[base + (size_t)m * 96 + c]) = lo;
            hi = split2(d[mf][nf][2], d[mf][nf][3], lo);
            *reinterpret_cast<uint32_t*>(&g_full_h[base + (size_t)(m + 8) * 96 + c]) = hi;
            *reinterpret_cast<uint32_t*>(&g_full_l[base + (size_t)(m + 8) * 96 + c]) = lo;
        }
    }
}

// =============================================================================
// Kernel 4: stage B via HMMA. part_z = full[rows][kslice] @ Wot[cols][kslice]^T
//   grid (24, 4, 3); block tile 128 x 128; K-chunk 32; warp tile 32 x 64.
// =============================================================================
__global__ void __launch_bounds__(256) stageB_hmma()
{
    __shared__ __nv_bfloat16 sAh[128 * SA_STRIDE];
    __shared__ __nv_bfloat16 sAl[128 * SA_STRIDE];
    __shared__ __nv_bfloat16 sBh[128 * SA_STRIDE];
    __shared__ __nv_bfloat16 sBl[128 * SA_STRIDE];

    const int tid = threadIdx.x;
    const int wid = tid >> 5, lane = tid & 31;
    const int row0 = blockIdx.x * 128;
    const int col0 = blockIdx.y * 128;
    const int z = blockIdx.z;
    const int wm = (wid & 3) * 32;
    const int wn = (wid >> 2) * 64;

    const uint32_t uAh = smem_u32(sAh), uAl = smem_u32(sAl);
    const uint32_t uBh = smem_u32(sBh), uBl = smem_u32(sBl);

    float d[2][8][4];
    #pragma unroll
    for (int mf = 0; mf < 2; mf++)
        #pragma unroll
        for (int nf = 0; nf < 8; nf++)
            #pragma unroll
            for (int q = 0; q < 4; q++) d[mf][nf][q] = 0.0f;

    for (int ch = 0; ch < 96; ch++) {
        const int t0 = z * 3072 + ch * 32;
        #pragma unroll
        for (int s = 0; s < 4; s++) {
            int item = tid + s * 256;            // 1024 uint2 per array
            int r = item >> 3, p4 = item & 7;
            uint2 va = *reinterpret_cast<const uint2*>(
                &g_full_h[(size_t)(row0 + r) * NSS + t0 + p4 * 4]);
            uint2 vb = *reinterpret_cast<const uint2*>(
                &g_full_l[(size_t)(row0 + r) * NSS + t0 + p4 * 4]);
            uint2 wa = *reinterpret_cast<const uint2*>(
                &g_Woth[(size_t)(col0 + r) * NSS + t0 + p4 * 4]);
            uint2 wb = *reinterpret_cast<const uint2*>(
                &g_Wotl[(size_t)(col0 + r) * NSS + t0 + p4 * 4]);
            *reinterpret_cast<uint2*>(&sAh[r * SA_STRIDE + p4 * 4]) = va;
            *reinterpret_cast<uint2*>(&sAl[r * SA_STRIDE + p4 * 4]) = vb;
            *reinterpret_cast<uint2*>(&sBh[r * SA_STRIDE + p4 * 4]) = wa;
            *reinterpret_cast<uint2*>(&sBl[r * SA_STRIDE + p4 * 4]) = wb;
        }
        __syncthreads();

        #pragma unroll
        for (int ks = 0; ks < 2; ks++) {
            const int k = ks * 16;
            uint32_t ah[2][4], al[2][4], bh[4][4], bl[4][4];
            #pragma unroll
            for (int mf = 0; mf < 2; mf++) {
                uint32_t off = (uint32_t)((wm + mf * 16 + (lane & 15)) * SA_STRIDE
                                          + k + (lane >> 4) * 8) * 2;
                ldsm_x4(ah[mf], uAh + off);
                ldsm_x4(al[mf], uAl + off);
            }
            #pragma unroll
            for (int nq = 0; nq < 4; nq++) {
                uint32_t off = (uint32_t)((wn + nq * 16 + (lane & 7) + ((lane >> 4) & 1) * 8)
                                          * SA_STRIDE + k + ((lane >> 3) & 1) * 8) * 2;
                ldsm_x4(bh[nq], uBh + off);
                ldsm_x4(bl[nq], uBl + off);
            }
            #pragma unroll
            for (int t3 = 0; t3 < 3; t3++) {
                uint32_t (*A)[4]  = (t3 == 2) ? al : ah;
                uint32_t (*Bf)[4] = (t3 == 1) ? bl : bh;
                #pragma unroll
                for (int mf = 0; mf < 2; mf++)
                    #pragma unroll
                    for (int nq = 0; nq < 4; nq++) {
                        mma_bf16(d[mf][nq * 2 + 0], A[mf], &Bf[nq][0]);
                        mma_bf16(d[mf][nq * 2 + 1], A[mf], &Bf[nq][2]);
                    }
            }
        }
        __syncthreads();
    }

    float* part = g_part[z];
    #pragma unroll
    for (int mf = 0; mf < 2; mf++) {
        int r = row0 + wm + mf * 16 + (lane >> 2);
        #pragma unroll
        for (int nf = 0; nf < 8; nf++) {
            int c = col0 + wn + nf * 8 + (lane & 3) * 2;
            *reinterpret_cast<float2*>(&part[(size_t)r * ND + c]) =
                make_float2(d[mf][nf][0], d[mf][nf][1]);
            *reinterpret_cast<float2*>(&part[(size_t)(r + 8) * ND + c]) =
                make_float2(d[mf][nf][2], d[mf][nf][3]);
        }
    }
}

// =============================================================================
// Kernel 5: out = p0 + p1 + p2 + bias
// =============================================================================
__global__ void __launch_bounds__(256) reduce_kernel(
    const float* __restrict__ bo, float* __restrict__ out)
{
    int idx = blockIdx.x * 256 + threadIdx.x;
    float4 a = reinterpret_cast<const float4*>(g_part[0])[idx];
    float4 b = reinterpret_cast<const float4*>(g_part[1])[idx];
    float4 c = reinterpret_cast<const float4*>(g_part[2])[idx];
    float4 bb = reinterpret_cast<const float4*>(bo)[idx & 127];
    float4 r;
    r.x = a.x + b.x + c.x + bb.x;
    r.y = a.y + b.y + c.y + bb.y;
    r.z = a.z + b.z + c.z + bb.z;
    r.w = a.w + b.w + c.w + bb.w;
    reinterpret_cast<float4*>(out)[idx] = r;
}

// =============================================================================
extern "C" void kernel_launch(void* const* d_in, const int* in_sizes, int n_in,
                              void* d_out, int out_size)
{
    (void)in_sizes; (void)n_in; (void)out_size;
    const float* queries = (const float*)d_in[0];
    const float* keys    = (const float*)d_in[1];
    const float* values  = (const float*)d_in[2];
    // d_in[3] = attn_mask (all false; no effect on the math)
    const float* Wq = (const float*)d_in[4];
    const float* bq = (const float*)d_in[5];
    const float* Wk = (const float*)d_in[6];
    const float* bk = (const float*)d_in[7];
    const float* Wv = (const float*)d_in[8];
    const float* bv = (const float*)d_in[9];
    const float* core = (const float*)d_in[10];
    const float* Wo = (const float*)d_in[11];
    const float* bo = (const float*)d_in[12];
    float* out = (float*)d_out;

    convWo_kernel<<<dim3(288, 16), 256>>>(Wo);
    proj_kernel<<<dim3(24, 8, 3), 256>>>(queries, keys, values,
                                         Wq, Wk, Wv, bq, bk, bv, core);
    convV_kernel<<<1536, 256>>>();
    stageA_hmma<<<dim3(72, 32), 256>>>();
    stageB_hmma<<<dim3(24, 4, 3), 256>>>();
    reduce_kernel<<<1536, 256>>>(bo, out);
}

// round 10
// speedup vs baseline: 4.8362x; 1.2330x over previous
#include <cuda_runtime.h>
#include <cuda_bf16.h>
#include <cstdint>

// B=32, L=96, S=96, D=512, H=8, DH=64, H*DH=512, S*S=9216, B*L=3072
#define NB 32
#define NL 96
#define NS 96
#define ND 512
#define NHD 512
#define NSS 9216
#define NROWS 3072

// ---------------- scratch (static device globals; no allocation) -------------
__device__ __align__(16) float g_AQ[NB * NL * NHD];            // [b][i][r]
__device__ __align__(16) float g_K [NB * NS * NHD];            // [b][j][r]
__device__ __align__(16) float g_V [NB * NS * NHD];            // [b][k][r]
__device__ __align__(16) __nv_bfloat16 g_Vh[NB * NS * NHD];
__device__ __align__(16) __nv_bfloat16 g_Vl[NB * NS * NHD];
__device__ __align__(16) __nv_bfloat16 g_full_h[(size_t)NROWS * NSS];
__device__ __align__(16) __nv_bfloat16 g_full_l[(size_t)NROWS * NSS];
__device__ __align__(16) __nv_bfloat16 g_Woth[ND * NSS];       // Wo^T hi: [c][t]
__device__ __align__(16) __nv_bfloat16 g_Wotl[ND * NSS];       // Wo^T lo: [c][t]
__device__ __align__(16) float g_part[3][NROWS * ND];

// ---------------- helpers -----------------------------------------------------
__device__ __forceinline__ uint32_t smem_u32(const void* p) {
    uint32_t a;
    asm("{ .reg .u64 t; cvta.to.shared.u64 t, %1; cvt.u32.u64 %0, t; }"
        : "=r"(a) : "l"(p));
    return a;
}
__device__ __forceinline__ void ldsm_x4(uint32_t r[4], uint32_t addr) {
    asm volatile("ldmatrix.sync.aligned.m8n8.x4.shared.b16 {%0,%1,%2,%3}, [%4];"
        : "=r"(r[0]), "=r"(r[1]), "=r"(r[2]), "=r"(r[3]) : "r"(addr));
}
__device__ __forceinline__ void mma_bf16(float d[4], const uint32_t a[4],
                                         const uint32_t* b) {
    asm volatile(
        "mma.sync.aligned.m16n8k16.row.col.f32.bf16.bf16.f32 "
        "{%0,%1,%2,%3}, {%4,%5,%6,%7}, {%8,%9}, {%0,%1,%2,%3};"
        : "+f"(d[0]), "+f"(d[1]), "+f"(d[2]), "+f"(d[3])
        : "r"(a[0]), "r"(a[1]), "r"(a[2]), "r"(a[3]), "r"(b[0]), "r"(b[1]));
}
__device__ __forceinline__ uint32_t split2(float a, float b, uint32_t &lo_out) {
    __nv_bfloat16 ha = __float2bfloat16(a), hb = __float2bfloat16(b);
    __nv_bfloat16 la = __float2bfloat16(a - __bfloat162float(ha));
    __nv_bfloat16 lb = __float2bfloat16(b - __bfloat162float(hb));
    lo_out = (uint32_t)__bfloat16_as_ushort(la) | ((uint32_t)__bfloat16_as_ushort(lb) << 16);
    return (uint32_t)__bfloat16_as_ushort(ha) | ((uint32_t)__bfloat16_as_ushort(hb) << 16);
}

// ---------------- packed f32x2 (projections) ----------------------------------
typedef unsigned long long u64;
__device__ __forceinline__ void fma2(u64 &d, u64 a, u64 b) {
    asm("fma.rn.f32x2 %0, %1, %2, %0;" : "+l"(d) : "l"(a), "l"(b));
}
__device__ __forceinline__ u64 lds2(const float* p) { return *reinterpret_cast<const u64*>(p); }
__device__ __forceinline__ float hsum2(u64 v) {
    return __uint_as_float((unsigned)(v & 0xffffffffull)) + __uint_as_float((unsigned)(v >> 32));
}

// =============================================================================
// Kernel 1: fused projections (fp32 FFMA2) — R4-proven
// =============================================================================
__global__ void __launch_bounds__(256) proj_kernel(
    const float* __restrict__ Xq, const float* __restrict__ Xk, const float* __restrict__ Xv,
    const float* __restrict__ Wq, const float* __restrict__ Wk, const float* __restrict__ Wv,
    const float* __restrict__ bq, const float* __restrict__ bk, const float* __restrict__ bv,
    const float* __restrict__ core)
{
    __shared__ float sX[128][34];
    __shared__ float sW[64][34];

    const int mode = blockIdx.z;
    const float* X    = mode == 0 ? Xq : (mode == 1 ? Xk : Xv);
    const float* W    = mode == 0 ? Wq : (mode == 1 ? Wk : Wv);
    const float* bias = mode == 0 ? bq : (mode == 1 ? bk : bv);

    const int tid = threadIdx.x;
    const int tx = tid & 15, ty = tid >> 4;
    const int row0 = blockIdx.x * 128;
    const int col0 = blockIdx.y * 64;

    u64 acc[8][4];
    #pragma unroll
    for (int u = 0; u < 8; u++)
        #pragma unroll
        for (int w = 0; w < 4; w++) acc[u][w] = 0ull;

    for (int k0 = 0; k0 < ND; k0 += 32) {
        #pragma unroll
        for (int t = 0; t < 8; t++) {
            int e2 = tid + t * 256;
            int row = e2 >> 4, c2 = e2 & 15;
            *reinterpret_cast<float2*>(&sX[row][c2 * 2]) =
                *reinterpret_cast<const float2*>(&X[(row0 + row) * ND + k0 + c2 * 2]);
        }
        #pragma unroll
        for (int t = 0; t < 2; t++) {
            int idx = tid + t * 256;
            int kk = idx >> 4, c4 = idx & 15;
            float4 wv = *reinterpret_cast<const float4*>(&W[(k0 + kk) * ND + col0 + c4 * 4]);
            sW[c4 * 4 + 0][kk] = wv.x;
            sW[c4 * 4 + 1][kk] = wv.y;
            sW[c4 * 4 + 2][kk] = wv.z;
            sW[c4 * 4 + 3][kk] = wv.w;
        }
        __syncthreads();
        #pragma unroll 2
        for (int kp = 0; kp < 16; kp++) {
            u64 a2[8], b2[4];
            #pragma unroll
            for (int u = 0; u < 8; u++) a2[u] = lds2(&sX[ty * 8 + u][2 * kp]);
            #pragma unroll
            for (int w = 0; w < 4; w++) b2[w] = lds2(&sW[tx + 16 * w][2 * kp]);
            #pragma unroll
            for (int u = 0; u < 8; u++)
                #pragma unroll
                for (int w = 0; w < 4; w++) fma2(acc[u][w], a2[u], b2[w]);
        }
        __syncthreads();
    }

    #pragma unroll
    for (int u = 0; u < 8; u++) {
        int r  = row0 + ty * 8 + u;
        int nh = r / 384;
        int rem = r - nh * 384;
        int bb = rem / 12;
        int t8 = rem - bb * 12;
        #pragma unroll
        for (int w = 0; w < 4; w++) {
            int c = col0 + tx + 16 * w;
            float val = hsum2(acc[u][w]) + bias[c];
            int ii = t8 * 8 + (c >> 6);
            int dd = c & 63;
            int nr = nh * 64 + dd;
            if (mode == 0)
                g_AQ[(bb * NL + ii) * NHD + nr] = val * core[nr] * 0.125f;
            else if (mode == 1)
                g_K[(bb * NS + ii) * NHD + nr] = val;
            else
                g_V[(bb * NS + ii) * NHD + nr] = val;
        }
    }
}

// =============================================================================
// Kernel 2a: V fp32 -> split bf16
// =============================================================================
__global__ void __launch_bounds__(256) convV_kernel()
{
    int idx = blockIdx.x * 256 + threadIdx.x;
    float4 v = reinterpret_cast<const float4*>(g_V)[idx];
    uint32_t l0, l1;
    uint32_t h0 = split2(v.x, v.y, l0);
    uint32_t h1 = split2(v.z, v.w, l1);
    reinterpret_cast<uint2*>(g_Vh)[idx] = make_uint2(h0, h1);
    reinterpret_cast<uint2*>(g_Vl)[idx] = make_uint2(l0, l1);
}

// =============================================================================
// Kernel 2b: Wo[t][c] -> Wot[c][t] split bf16 (tiled transpose)
// =============================================================================
__global__ void __launch_bounds__(256) convWo_kernel(const float* __restrict__ Wo)
{
    __shared__ float tile[32][33];
    const int t0 = blockIdx.x * 32;
    const int c0 = blockIdx.y * 32;
    const int tx = threadIdx.x & 31, ty = threadIdx.x >> 5;
    #pragma unroll
    for (int s = 0; s < 4; s++)
        tile[ty + 8 * s][tx] = Wo[(size_t)(t0 + ty + 8 * s) * ND + c0 + tx];
    __syncthreads();
    #pragma unroll
    for (int s = 0; s < 4; s++) {
        float f = tile[tx][ty + 8 * s];
        __nv_bfloat16 h = __float2bfloat16(f);
        __nv_bfloat16 l = __float2bfloat16(f - __bfloat162float(h));
        size_t o = (size_t)(c0 + ty + 8 * s) * NSS + t0 + tx;
        g_Woth[o] = h;
        g_Wotl[o] = l;
    }
}

// =============================================================================
// Kernel 3: stage A via HMMA (mma.sync m16n8k16 bf16, 3-term split)
//   per b: full[m=i*96+j][k] = sum_r (AQ[i,r]*K[j,r]) * V[k,r]
//   grid (72, 32); block tile 128(m) x 96(n); K-chunk 32; 8 warps = 4m x 2n.
//   __launch_bounds__(256, 2): cap regs at 128 -> 2 CTAs/SM (occ 12.5% -> 25%)
// =============================================================================
#define SA_STRIDE 40   // bf16 elems per row (32 + 8 pad) -> 80B, ldmatrix conflict-free
__global__ void __launch_bounds__(256, 2) stageA_hmma()
{
    __shared__ __nv_bfloat16 sAh[128 * SA_STRIDE];
    __shared__ __nv_bfloat16 sAl[128 * SA_STRIDE];
    __shared__ __nv_bfloat16 sBh[96 * SA_STRIDE];
    __shared__ __nv_bfloat16 sBl[96 * SA_STRIDE];
    __shared__ float AQ_s[2 * 32];

    const int tid = threadIdx.x;
    const int wid = tid >> 5, lane = tid & 31;
    const int t = blockIdx.x;
    const int b = blockIdx.y;
    const int i0 = (t * 128) / 96;
    const int wm = (wid & 3) * 32;     // warp m origin in tile
    const int wn = (wid >> 2) * 48;    // warp n origin in tile

    const uint32_t uAh = smem_u32(sAh), uAl = smem_u32(sAl);
    const uint32_t uBh = smem_u32(sBh), uBl = smem_u32(sBl);

    const float* Kg  = g_K  + (size_t)(b * NS) * NHD;
    const float* AQg = g_AQ + (size_t)(b * NL) * NHD;
    const __nv_bfloat16* Vhg = g_Vh + (size_t)(b * NS) * NHD;
    const __nv_bfloat16* Vlg = g_Vl + (size_t)(b * NS) * NHD;

    float d[2][6][4];
    #pragma unroll
    for (int mf = 0; mf < 2; mf++)
        #pragma unroll
        for (int nf = 0; nf < 6; nf++)
            #pragma unroll
            for (int q = 0; q < 4; q++) d[mf][nf][q] = 0.0f;

    for (int ch = 0; ch < 16; ch++) {
        const int r0 = ch * 32;
        // AQ chunk (2 rows x 32)
        if (tid < 64)
            AQ_s[tid] = AQg[(size_t)(i0 + (tid >> 5)) * NHD + r0 + (tid & 31)];
        // V hi/lo -> sB (96 rows x 4 uint2)
        #pragma unroll
        for (int s = 0; s < 3; s++) {
            int item = tid + s * 256;            // 768 uint2
            int n = item >> 3, p4 = item & 7;
            uint2 vh = *reinterpret_cast<const uint2*>(&Vhg[(size_t)n * NHD + r0 + p4 * 4]);
            uint2 vl = *reinterpret_cast<const uint2*>(&Vlg[(size_t)n * NHD + r0 + p4 * 4]);
            *reinterpret_cast<uint2*>(&sBh[n * SA_STRIDE + p4 * 4]) = vh;
            *reinterpret_cast<uint2*>(&sBl[n * SA_STRIDE + p4 * 4]) = vl;
        }
        __syncthreads();   // AQ_s ready before build reads it
        // build A = AQ*K split (128 rows x 8 quads)
        #pragma unroll
        for (int s = 0; s < 4; s++) {
            int item = tid + s * 256;            // 1024 quads
            int mrow = item >> 3, p4 = item & 7;
            int m = t * 128 + mrow;
            int i = m / 96;
            int j = m - i * 96;
            int isel = i - i0;
            float4 kv = *reinterpret_cast<const float4*>(&Kg[(size_t)j * NHD + r0 + p4 * 4]);
            float4 qv = *reinterpret_cast<const float4*>(&AQ_s[isel * 32 + p4 * 4]);
            uint32_t lo0, lo1;
            uint32_t hi0 = split2(qv.x * kv.x, qv.y * kv.y, lo0);
            uint32_t hi1 = split2(qv.z * kv.z, qv.w * kv.w, lo1);
            *reinterpret_cast<uint2*>(&sAh[mrow * SA_STRIDE + p4 * 4]) = make_uint2(hi0, hi1);
            *reinterpret_cast<uint2*>(&sAl[mrow * SA_STRIDE + p4 * 4]) = make_uint2(lo0, lo1);
        }
        __syncthreads();

        #pragma unroll
        for (int ks = 0; ks < 2; ks++) {
            const int k = ks * 16;
            uint32_t ah[2][4], al[2][4], bh[3][4], bl[3][4];
            #pragma unroll
            for (int mf = 0; mf < 2; mf++) {
                uint32_t off = (uint32_t)((wm + mf * 16 + (lane & 15)) * SA_STRIDE
                                          + k + (lane >> 4) * 8) * 2;
                ldsm_x4(ah[mf], uAh + off);
                ldsm_x4(al[mf], uAl + off);
            }
            #pragma unroll
            for (int nq = 0; nq < 3; nq++) {
                uint32_t off = (uint32_t)((wn + nq * 16 + (lane & 7) + ((lane >> 4) & 1) * 8)
                                          * SA_STRIDE + k + ((lane >> 3) & 1) * 8) * 2;
                ldsm_x4(bh[nq], uBh + off);
                ldsm_x4(bl[nq], uBl + off);
            }
            #pragma unroll
            for (int t3 = 0; t3 < 3; t3++) {
                uint32_t (*A)[4]  = (t3 == 2) ? al : ah;
                uint32_t (*Bf)[4] = (t3 == 1) ? bl : bh;
                #pragma unroll
                for (int mf = 0; mf < 2; mf++)
                    #pragma unroll
                    for (int nq = 0; nq < 3; nq++) {
                        mma_bf16(d[mf][nq * 2 + 0], A[mf], &Bf[nq][0]);
                        mma_bf16(d[mf][nq * 2 + 1], A[mf], &Bf[nq][2]);
                    }
            }
        }
        __syncthreads();
    }

    // epilogue: split-bf16 store of D fragments into g_full
    const size_t base = (size_t)b * ((size_t)NL * NSS);
    #pragma unroll
    for (int mf = 0; mf < 2; mf++) {
        int m = t * 128 + wm + mf * 16 + (lane >> 2);
        #pragma unroll
        for (int nf = 0; nf < 6; nf++) {
            int c = wn + nf * 8 + (lane & 3) * 2;
            uint32_t lo, hi;
            hi = split2(d[mf][nf][0], d[mf][nf][1], lo);
            *reinterpret_cast<uint32_t*>(&g_full_h[base + (size_t)m * 96 + c]) = hi;
            *reinterpret_cast<uint32_t*>(&g_full_l[base + (size_t)m * 96 + c]) = lo;
            hi = split2(d[mf][nf][2], d[mf][nf][3], lo);
            *reinterpret_cast<uint32_t*>(&g_full_h[base + (size_t)(m + 8) * 96 + c]) = hi;
            *reinterpret_cast<uint32_t*>(&g_full_l[base + (size_t)(m + 8) * 96 + c]) = lo;
        }
    }
}

// =============================================================================
// Kernel 4: stage B via HMMA. part_z = full[rows][kslice] @ Wot[cols][kslice]^T
//   grid (24, 4, 3); block tile 128 x 128; K-chunk 32; warp tile 32 x 64.
//   __launch_bounds__(256, 2): 2 CTAs/SM for latency hiding.
// =============================================================================
__global__ void __launch_bounds__(256, 2) stageB_hmma()
{
    __shared__ __nv_bfloat16 sAh[128 * SA_STRIDE];
    __shared__ __nv_bfloat16 sAl[128 * SA_STRIDE];
    __shared__ __nv_bfloat16 sBh[128 * SA_STRIDE];
    __shared__ __nv_bfloat16 sBl[128 * SA_STRIDE];

    const int tid = threadIdx.x;
    const int wid = tid >> 5, lane = tid & 31;
    const int row0 = blockIdx.x * 128;
    const int col0 = blockIdx.y * 128;
    const int z = blockIdx.z;
    const int wm = (wid & 3) * 32;
    const int wn = (wid >> 2) * 64;

    const uint32_t uAh = smem_u32(sAh), uAl = smem_u32(sAl);
    const uint32_t uBh = smem_u32(sBh), uBl = smem_u32(sBl);

    float d[2][8][4];
    #pragma unroll
    for (int mf = 0; mf < 2; mf++)
        #pragma unroll
        for (int nf = 0; nf < 8; nf++)
            #pragma unroll
            for (int q = 0; q < 4; q++) d[mf][nf][q] = 0.0f;

    for (int ch = 0; ch < 96; ch++) {
        const int t0 = z * 3072 + ch * 32;
        #pragma unroll
        for (int s = 0; s < 4; s++) {
            int item = tid + s * 256;            // 1024 uint2 per array
            int r = item >> 3, p4 = item & 7;
            uint2 va = *reinterpret_cast<const uint2*>(
                &g_full_h[(size_t)(row0 + r) * NSS + t0 + p4 * 4]);
            uint2 vb = *reinterpret_cast<const uint2*>(
                &g_full_l[(size_t)(row0 + r) * NSS + t0 + p4 * 4]);
            uint2 wa = *reinterpret_cast<const uint2*>(
                &g_Woth[(size_t)(col0 + r) * NSS + t0 + p4 * 4]);
            uint2 wb = *reinterpret_cast<const uint2*>(
                &g_Wotl[(size_t)(col0 + r) * NSS + t0 + p4 * 4]);
            *reinterpret_cast<uint2*>(&sAh[r * SA_STRIDE + p4 * 4]) = va;
            *reinterpret_cast<uint2*>(&sAl[r * SA_STRIDE + p4 * 4]) = vb;
            *reinterpret_cast<uint2*>(&sBh[r * SA_STRIDE + p4 * 4]) = wa;
            *reinterpret_cast<uint2*>(&sBl[r * SA_STRIDE + p4 * 4]) = wb;
        }
        __syncthreads();

        #pragma unroll
        for (int ks = 0; ks < 2; ks++) {
            const int k = ks * 16;
            uint32_t ah[2][4], al[2][4], bh[4][4], bl[4][4];
            #pragma unroll
            for (int mf = 0; mf < 2; mf++) {
                uint32_t off = (uint32_t)((wm + mf * 16 + (lane & 15)) * SA_STRIDE
                                          + k + (lane >> 4) * 8) * 2;
                ldsm_x4(ah[mf], uAh + off);
                ldsm_x4(al[mf], uAl + off);
            }
            #pragma unroll
            for (int nq = 0; nq < 4; nq++) {
                uint32_t off = (uint32_t)((wn + nq * 16 + (lane & 7) + ((lane >> 4) & 1) * 8)
                                          * SA_STRIDE + k + ((lane >> 3) & 1) * 8) * 2;
                ldsm_x4(bh[nq], uBh + off);
                ldsm_x4(bl[nq], uBl + off);
            }
            #pragma unroll
            for (int t3 = 0; t3 < 3; t3++) {
                uint32_t (*A)[4]  = (t3 == 2) ? al : ah;
                uint32_t (*Bf)[4] = (t3 == 1) ? bl : bh;
                #pragma unroll
                for (int mf = 0; mf < 2; mf++)
                    #pragma unroll
                    for (int nq = 0; nq < 4; nq++) {
                        mma_bf16(d[mf][nq * 2 + 0], A[mf], &Bf[nq][0]);
                        mma_bf16(d[mf][nq * 2 + 1], A[mf], &Bf[nq][2]);
                    }
            }
        }
        __syncthreads();
    }

    float* part = g_part[z];
    #pragma unroll
    for (int mf = 0; mf < 2; mf++) {
        int r = row0 + wm + mf * 16 + (lane >> 2);
        #pragma unroll
        for (int nf = 0; nf < 8; nf++) {
            int c = col0 + wn + nf * 8 + (lane & 3) * 2;
            *reinterpret_cast<float2*>(&part[(size_t)r * ND + c]) =
                make_float2(d[mf][nf][0], d[mf][nf][1]);
            *reinterpret_cast<float2*>(&part[(size_t)(r + 8) * ND + c]) =
                make_float2(d[mf][nf][2], d[mf][nf][3]);
        }
    }
}

// =============================================================================
// Kernel 5: out = p0 + p1 + p2 + bias
// =============================================================================
__global__ void __launch_bounds__(256) reduce_kernel(
    const float* __restrict__ bo, float* __restrict__ out)
{
    int idx = blockIdx.x * 256 + threadIdx.x;
    float4 a = reinterpret_cast<const float4*>(g_part[0])[idx];
    float4 b = reinterpret_cast<const float4*>(g_part[1])[idx];
    float4 c = reinterpret_cast<const float4*>(g_part[2])[idx];
    float4 bb = reinterpret_cast<const float4*>(bo)[idx & 127];
    float4 r;
    r.x = a.x + b.x + c.x + bb.x;
    r.y = a.y + b.y + c.y + bb.y;
    r.z = a.z + b.z + c.z + bb.z;
    r.w = a.w + b.w + c.w + bb.w;
    reinterpret_cast<float4*>(out)[idx] = r;
}

// =============================================================================
extern "C" void kernel_launch(void* const* d_in, const int* in_sizes, int n_in,
                              void* d_out, int out_size)
{
    (void)in_sizes; (void)n_in; (void)out_size;
    const float* queries = (const float*)d_in[0];
    const float* keys    = (const float*)d_in[1];
    const float* values  = (const float*)d_in[2];
    // d_in[3] = attn_mask (all false; no effect on the math)
    const float* Wq = (const float*)d_in[4];
    const float* bq = (const float*)d_in[5];
    const float* Wk = (const float*)d_in[6];
    const float* bk = (const float*)d_in[7];
    const float* Wv = (const float*)d_in[8];
    const float* bv = (const float*)d_in[9];
    const float* core = (const float*)d_in[10];
    const float* Wo = (const float*)d_in[11];
    const float* bo = (const float*)d_in[12];
    float* out = (float*)d_out;

    convWo_kernel<<<dim3(288, 16), 256>>>(Wo);
    proj_kernel<<<dim3(24, 8, 3), 256>>>(queries, keys, values,
                                         Wq, Wk, Wv, bq, bk, bv, core);
    convV_kernel<<<1536, 256>>>();
    stageA_hmma<<<dim3(72, 32), 256>>>();
    stageB_hmma<<<dim3(24, 4, 3), 256>>>();
    reduce_kernel<<<1536, 256>>>(bo, out);
}

// round 11
// speedup vs baseline: 5.3439x; 1.1050x over previous
#include <cuda_runtime.h>
#include <cuda_bf16.h>
#include <cstdint>

// B=32, L=96, S=96, D=512, H=8, DH=64, H*DH=512, S*S=9216, B*L=3072
#define NB 32
#define NL 96
#define NS 96
#define ND 512
#define NHD 512
#define NSS 9216
#define NROWS 3072

// ---------------- scratch (static device globals; no allocation) -------------
__device__ __align__(16) float g_AQ[NB * NL * NHD];            // [b][i][r]
__device__ __align__(16) float g_K [NB * NS * NHD];            // [b][j][r]
__device__ __align__(16) float g_V [NB * NS * NHD];            // [b][k][r]
__device__ __align__(16) __nv_bfloat16 g_Vh[NB * NS * NHD];
__device__ __align__(16) __nv_bfloat16 g_Vl[NB * NS * NHD];
__device__ __align__(16) __nv_bfloat16 g_full_h[(size_t)NROWS * NSS];
__device__ __align__(16) __nv_bfloat16 g_full_l[(size_t)NROWS * NSS];
__device__ __align__(16) __nv_bfloat16 g_Woth[ND * NSS];       // Wo^T hi: [c][t]
__device__ __align__(16) __nv_bfloat16 g_Wotl[ND * NSS];       // Wo^T lo: [c][t]
__device__ __align__(16) float g_part[3][NROWS * ND];

// ---------------- helpers -----------------------------------------------------
__device__ __forceinline__ uint32_t smem_u32(const void* p) {
    uint32_t a;
    asm("{ .reg .u64 t; cvta.to.shared.u64 t, %1; cvt.u32.u64 %0, t; }"
        : "=r"(a) : "l"(p));
    return a;
}
__device__ __forceinline__ void ldsm_x4(uint32_t r[4], uint32_t addr) {
    asm volatile("ldmatrix.sync.aligned.m8n8.x4.shared.b16 {%0,%1,%2,%3}, [%4];"
        : "=r"(r[0]), "=r"(r[1]), "=r"(r[2]), "=r"(r[3]) : "r"(addr));
}
__device__ __forceinline__ void mma_bf16(float d[4], const uint32_t a[4],
                                         const uint32_t* b) {
    asm volatile(
        "mma.sync.aligned.m16n8k16.row.col.f32.bf16.bf16.f32 "
        "{%0,%1,%2,%3}, {%4,%5,%6,%7}, {%8,%9}, {%0,%1,%2,%3};"
        : "+f"(d[0]), "+f"(d[1]), "+f"(d[2]), "+f"(d[3])
        : "r"(a[0]), "r"(a[1]), "r"(a[2]), "r"(a[3]), "r"(b[0]), "r"(b[1]));
}
__device__ __forceinline__ uint32_t split2(float a, float b, uint32_t &lo_out) {
    __nv_bfloat16 ha = __float2bfloat16(a), hb = __float2bfloat16(b);
    __nv_bfloat16 la = __float2bfloat16(a - __bfloat162float(ha));
    __nv_bfloat16 lb = __float2bfloat16(b - __bfloat162float(hb));
    lo_out = (uint32_t)__bfloat16_as_ushort(la) | ((uint32_t)__bfloat16_as_ushort(lb) << 16);
    return (uint32_t)__bfloat16_as_ushort(ha) | ((uint32_t)__bfloat16_as_ushort(hb) << 16);
}

// ---------------- packed f32x2 (projections) ----------------------------------
typedef unsigned long long u64;
__device__ __forceinline__ void fma2(u64 &d, u64 a, u64 b) {
    asm("fma.rn.f32x2 %0, %1, %2, %0;" : "+l"(d) : "l"(a), "l"(b));
}
__device__ __forceinline__ u64 lds2(const float* p) { return *reinterpret_cast<const u64*>(p); }
__device__ __forceinline__ float hsum2(u64 v) {
    return __uint_as_float((unsigned)(v & 0xffffffffull)) + __uint_as_float((unsigned)(v >> 32));
}

// =============================================================================
// Kernel 1: fused projections (fp32 FFMA2) — R4-proven
// =============================================================================
__global__ void __launch_bounds__(256) proj_kernel(
    const float* __restrict__ Xq, const float* __restrict__ Xk, const float* __restrict__ Xv,
    const float* __restrict__ Wq, const float* __restrict__ Wk, const float* __restrict__ Wv,
    const float* __restrict__ bq, const float* __restrict__ bk, const float* __restrict__ bv,
    const float* __restrict__ core)
{
    __shared__ float sX[128][34];
    __shared__ float sW[64][34];

    const int mode = blockIdx.z;
    const float* X    = mode == 0 ? Xq : (mode == 1 ? Xk : Xv);
    const float* W    = mode == 0 ? Wq : (mode == 1 ? Wk : Wv);
    const float* bias = mode == 0 ? bq : (mode == 1 ? bk : bv);

    const int tid = threadIdx.x;
    const int tx = tid & 15, ty = tid >> 4;
    const int row0 = blockIdx.x * 128;
    const int col0 = blockIdx.y * 64;

    u64 acc[8][4];
    #pragma unroll
    for (int u = 0; u < 8; u++)
        #pragma unroll
        for (int w = 0; w < 4; w++) acc[u][w] = 0ull;

    for (int k0 = 0; k0 < ND; k0 += 32) {
        #pragma unroll
        for (int t = 0; t < 8; t++) {
            int e2 = tid + t * 256;
            int row = e2 >> 4, c2 = e2 & 15;
            *reinterpret_cast<float2*>(&sX[row][c2 * 2]) =
                *reinterpret_cast<const float2*>(&X[(row0 + row) * ND + k0 + c2 * 2]);
        }
        #pragma unroll
        for (int t = 0; t < 2; t++) {
            int idx = tid + t * 256;
            int kk = idx >> 4, c4 = idx & 15;
            float4 wv = *reinterpret_cast<const float4*>(&W[(k0 + kk) * ND + col0 + c4 * 4]);
            sW[c4 * 4 + 0][kk] = wv.x;
            sW[c4 * 4 + 1][kk] = wv.y;
            sW[c4 * 4 + 2][kk] = wv.z;
            sW[c4 * 4 + 3][kk] = wv.w;
        }
        __syncthreads();
        #pragma unroll 2
        for (int kp = 0; kp < 16; kp++) {
            u64 a2[8], b2[4];
            #pragma unroll
            for (int u = 0; u < 8; u++) a2[u] = lds2(&sX[ty * 8 + u][2 * kp]);
            #pragma unroll
            for (int w = 0; w < 4; w++) b2[w] = lds2(&sW[tx + 16 * w][2 * kp]);
            #pragma unroll
            for (int u = 0; u < 8; u++)
                #pragma unroll
                for (int w = 0; w < 4; w++) fma2(acc[u][w], a2[u], b2[w]);
        }
        __syncthreads();
    }

    #pragma unroll
    for (int u = 0; u < 8; u++) {
        int r  = row0 + ty * 8 + u;
        int nh = r / 384;
        int rem = r - nh * 384;
        int bb = rem / 12;
        int t8 = rem - bb * 12;
        #pragma unroll
        for (int w = 0; w < 4; w++) {
            int c = col0 + tx + 16 * w;
            float val = hsum2(acc[u][w]) + bias[c];
            int ii = t8 * 8 + (c >> 6);
            int dd = c & 63;
            int nr = nh * 64 + dd;
            if (mode == 0)
                g_AQ[(bb * NL + ii) * NHD + nr] = val * core[nr] * 0.125f;
            else if (mode == 1)
                g_K[(bb * NS + ii) * NHD + nr] = val;
            else
                g_V[(bb * NS + ii) * NHD + nr] = val;
        }
    }
}

// =============================================================================
// Kernel 2a: V fp32 -> split bf16
// =============================================================================
__global__ void __launch_bounds__(256) convV_kernel()
{
    int idx = blockIdx.x * 256 + threadIdx.x;
    float4 v = reinterpret_cast<const float4*>(g_V)[idx];
    uint32_t l0, l1;
    uint32_t h0 = split2(v.x, v.y, l0);
    uint32_t h1 = split2(v.z, v.w, l1);
    reinterpret_cast<uint2*>(g_Vh)[idx] = make_uint2(h0, h1);
    reinterpret_cast<uint2*>(g_Vl)[idx] = make_uint2(l0, l1);
}

// =============================================================================
// Kernel 2b: Wo[t][c] -> Wot[c][t] split bf16 (tiled transpose)
// =============================================================================
__global__ void __launch_bounds__(256) convWo_kernel(const float* __restrict__ Wo)
{
    __shared__ float tile[32][33];
    const int t0 = blockIdx.x * 32;
    const int c0 = blockIdx.y * 32;
    const int tx = threadIdx.x & 31, ty = threadIdx.x >> 5;
    #pragma unroll
    for (int s = 0; s < 4; s++)
        tile[ty + 8 * s][tx] = Wo[(size_t)(t0 + ty + 8 * s) * ND + c0 + tx];
    __syncthreads();
    #pragma unroll
    for (int s = 0; s < 4; s++) {
        float f = tile[tx][ty + 8 * s];
        __nv_bfloat16 h = __float2bfloat16(f);
        __nv_bfloat16 l = __float2bfloat16(f - __bfloat162float(h));
        size_t o = (size_t)(c0 + ty + 8 * s) * NSS + t0 + tx;
        g_Woth[o] = h;
        g_Wotl[o] = l;
    }
}

// =============================================================================
// Kernel 3: stage A via HMMA, K-chunk 64, dynamic smem.
//   per b: full[m=i*96+j][k] = sum_r (AQ[i,r]*K[j,r]) * V[k,r]
//   grid (72, 32); tile 128m x 96n; 8 warps = 4m x 2n; 2 CTAs/SM.
//   dyn layout: sAh[0,18432) sAl[18432,36864) sBh[36864,50688)
//               sBl[50688,64512) AQ_s[64512,68608)
// =============================================================================
#define SA_STR 72          // bf16 per row (64 + 8 pad); 144B stride, ldsm conflict-free
#define SA_OAL 18432
#define SA_OBH 36864
#define SA_OBL 50688
#define SA_OAQ 64512
#define SA_SMEM 68608
__global__ void __launch_bounds__(256, 2) stageA_hmma()
{
    extern __shared__ __align__(16) char dyn[];
    __nv_bfloat16* sAh = reinterpret_cast<__nv_bfloat16*>(dyn);
    __nv_bfloat16* sAl = reinterpret_cast<__nv_bfloat16*>(dyn + SA_OAL);
    __nv_bfloat16* sBh = reinterpret_cast<__nv_bfloat16*>(dyn + SA_OBH);
    __nv_bfloat16* sBl = reinterpret_cast<__nv_bfloat16*>(dyn + SA_OBL);
    float* AQ_s        = reinterpret_cast<float*>(dyn + SA_OAQ);

    const int tid = threadIdx.x;
    const int wid = tid >> 5, lane = tid & 31;
    const int t = blockIdx.x;
    const int b = blockIdx.y;
    const int i0 = (t * 128) / 96;
    const int wm = (wid & 3) * 32;
    const int wn = (wid >> 2) * 48;

    const uint32_t uAh = smem_u32(sAh), uAl = smem_u32(sAl);
    const uint32_t uBh = smem_u32(sBh), uBl = smem_u32(sBl);

    const float* Kg  = g_K  + (size_t)(b * NS) * NHD;
    const float* AQg = g_AQ + (size_t)(b * NL) * NHD;
    const __nv_bfloat16* Vhg = g_Vh + (size_t)(b * NS) * NHD;
    const __nv_bfloat16* Vlg = g_Vl + (size_t)(b * NS) * NHD;

    // preload both AQ rows once (2 x 512 fp32 = 256 float4, 1/thread)
    {
        int row = tid >> 7, col = (tid & 127) * 4;
        *reinterpret_cast<float4*>(&AQ_s[row * 512 + col]) =
            *reinterpret_cast<const float4*>(&AQg[(size_t)(i0 + row) * NHD + col]);
    }

    float d[2][6][4];
    #pragma unroll
    for (int mf = 0; mf < 2; mf++)
        #pragma unroll
        for (int nf = 0; nf < 6; nf++)
            #pragma unroll
            for (int q = 0; q < 4; q++) d[mf][nf][q] = 0.0f;

    for (int ch = 0; ch < 8; ch++) {
        const int r0 = ch * 64;
        // V hi/lo -> sB: 2 arrays x 96 rows x 8 uint4 = 1536 items, 6/thread
        #pragma unroll
        for (int s = 0; s < 6; s++) {
            int item = tid + s * 256;                  // 0..1535
            int arr = (item >= 768) ? 1 : 0;
            int idx = item - arr * 768;                // 768 not pow2: subtract
            int n = idx >> 3, seg = idx & 7;           // n<96, seg<8 (8 bf16 each)
            const __nv_bfloat16* src = (arr ? Vlg : Vhg)
                + (size_t)n * NHD + r0 + seg * 8;
            __nv_bfloat16* dst = (arr ? sBl : sBh) + n * SA_STR + seg * 8;
            *reinterpret_cast<uint4*>(dst) = *reinterpret_cast<const uint4*>(src);
        }
        __syncthreads();   // AQ_s (first iter) + nothing else ordered here
        // build A = AQ*K split: 128 rows x 16 quads = 2048 items, 8/thread
        #pragma unroll
        for (int s = 0; s < 8; s++) {
            int item = tid + s * 256;
            int mrow = item >> 4, p4 = item & 15;
            int m = t * 128 + mrow;
            int i = m / 96;
            int j = m - i * 96;
            int isel = i - i0;
            float4 kv = *reinterpret_cast<const float4*>(&Kg[(size_t)j * NHD + r0 + p4 * 4]);
            float4 qv = *reinterpret_cast<const float4*>(&AQ_s[isel * 512 + r0 + p4 * 4]);
            uint32_t lo0, lo1;
            uint32_t hi0 = split2(qv.x * kv.x, qv.y * kv.y, lo0);
            uint32_t hi1 = split2(qv.z * kv.z, qv.w * kv.w, lo1);
            *reinterpret_cast<uint2*>(&sAh[mrow * SA_STR + p4 * 4]) = make_uint2(hi0, hi1);
            *reinterpret_cast<uint2*>(&sAl[mrow * SA_STR + p4 * 4]) = make_uint2(lo0, lo1);
        }
        __syncthreads();

        #pragma unroll
        for (int ks = 0; ks < 4; ks++) {
            const int k = ks * 16;
            uint32_t ah[2][4], al[2][4], bh[3][4], bl[3][4];
            #pragma unroll
            for (int mf = 0; mf < 2; mf++) {
                uint32_t off = (uint32_t)((wm + mf * 16 + (lane & 15)) * SA_STR
                                          + k + (lane >> 4) * 8) * 2;
                ldsm_x4(ah[mf], uAh + off);
                ldsm_x4(al[mf], uAl + off);
            }
            #pragma unroll
            for (int nq = 0; nq < 3; nq++) {
                uint32_t off = (uint32_t)((wn + nq * 16 + (lane & 7) + ((lane >> 4) & 1) * 8)
                                          * SA_STR + k + ((lane >> 3) & 1) * 8) * 2;
                ldsm_x4(bh[nq], uBh + off);
                ldsm_x4(bl[nq], uBl + off);
            }
            #pragma unroll
            for (int t3 = 0; t3 < 3; t3++) {
                uint32_t (*A)[4]  = (t3 == 2) ? al : ah;
                uint32_t (*Bf)[4] = (t3 == 1) ? bl : bh;
                #pragma unroll
                for (int mf = 0; mf < 2; mf++)
                    #pragma unroll
                    for (int nq = 0; nq < 3; nq++) {
                        mma_bf16(d[mf][nq * 2 + 0], A[mf], &Bf[nq][0]);
                        mma_bf16(d[mf][nq * 2 + 1], A[mf], &Bf[nq][2]);
                    }
            }
        }
        __syncthreads();
    }

    // epilogue: split-bf16 store of D fragments into g_full
    const size_t base = (size_t)b * ((size_t)NL * NSS);
    #pragma unroll
    for (int mf = 0; mf < 2; mf++) {
        int m = t * 128 + wm + mf * 16 + (lane >> 2);
        #pragma unroll
        for (int nf = 0; nf < 6; nf++) {
            int c = wn + nf * 8 + (lane & 3) * 2;
            uint32_t lo, hi;
            hi = split2(d[mf][nf][0], d[mf][nf][1], lo);
            *reinterpret_cast<uint32_t*>(&g_full_h[base + (size_t)m * 96 + c]) = hi;
            *reinterpret_cast<uint32_t*>(&g_full_l[base + (size_t)m * 96 + c]) = lo;
            hi = split2(d[mf][nf][2], d[mf][nf][3], lo);
            *reinterpret_cast<uint32_t*>(&g_full_h[base + (size_t)(m + 8) * 96 + c]) = hi;
            *reinterpret_cast<uint32_t*>(&g_full_l[base + (size_t)(m + 8) * 96 + c]) = lo;
        }
    }
}

// =============================================================================
// Kernel 4: stage B via HMMA, K-chunk 64, dynamic smem.
//   part_z = full[rows][kslice] @ Wot[cols][kslice]^T; grid (24, 4, 3).
//   tile 128x128; warp 32x64; 2 CTAs/SM.
//   dyn layout: sAh[0) sAl[18432) sBh[36864) sBl[55296); total 73728
// =============================================================================
#define SB_OAL 18432
#define SB_OBH 36864
#define SB_OBL 55296
#define SB_SMEM 73728
__global__ void __launch_bounds__(256, 2) stageB_hmma()
{
    extern __shared__ __align__(16) char dyn[];
    __nv_bfloat16* sAh = reinterpret_cast<__nv_bfloat16*>(dyn);
    __nv_bfloat16* sAl = reinterpret_cast<__nv_bfloat16*>(dyn + SB_OAL);
    __nv_bfloat16* sBh = reinterpret_cast<__nv_bfloat16*>(dyn + SB_OBH);
    __nv_bfloat16* sBl = reinterpret_cast<__nv_bfloat16*>(dyn + SB_OBL);

    const int tid = threadIdx.x;
    const int wid = tid >> 5, lane = tid & 31;
    const int row0 = blockIdx.x * 128;
    const int col0 = blockIdx.y * 128;
    const int z = blockIdx.z;
    const int wm = (wid & 3) * 32;
    const int wn = (wid >> 2) * 64;

    const uint32_t uAh = smem_u32(sAh), uAl = smem_u32(sAl);
    const uint32_t uBh = smem_u32(sBh), uBl = smem_u32(sBl);

    float d[2][8][4];
    #pragma unroll
    for (int mf = 0; mf < 2; mf++)
        #pragma unroll
        for (int nf = 0; nf < 8; nf++)
            #pragma unroll
            for (int q = 0; q < 4; q++) d[mf][nf][q] = 0.0f;

    for (int ch = 0; ch < 48; ch++) {
        const int t0 = z * 3072 + ch * 64;
        // 4 arrays x 128 rows x 8 uint4 = 4096 items, 16/thread
        #pragma unroll
        for (int s = 0; s < 16; s++) {
            int item = tid + s * 256;
            int arr = item >> 10;                      // 0..3 (1024 pow2)
            int idx = item & 1023;
            int r = idx >> 3, seg = idx & 7;
            const __nv_bfloat16* src;
            __nv_bfloat16* dst;
            if (arr == 0)      { src = &g_full_h[(size_t)(row0 + r) * NSS + t0 + seg * 8]; dst = sAh; }
            else if (arr == 1) { src = &g_full_l[(size_t)(row0 + r) * NSS + t0 + seg * 8]; dst = sAl; }
            else if (arr == 2) { src = &g_Woth[(size_t)(col0 + r) * NSS + t0 + seg * 8];   dst = sBh; }
            else               { src = &g_Wotl[(size_t)(col0 + r) * NSS + t0 + seg * 8];   dst = sBl; }
            *reinterpret_cast<uint4*>(dst + r * SA_STR + seg * 8) =
                *reinterpret_cast<const uint4*>(src);
        }
        __syncthreads();

        #pragma unroll
        for (int ks = 0; ks < 4; ks++) {
            const int k = ks * 16;
            uint32_t ah[2][4], al[2][4], bh[4][4], bl[4][4];
            #pragma unroll
            for (int mf = 0; mf < 2; mf++) {
                uint32_t off = (uint32_t)((wm + mf * 16 + (lane & 15)) * SA_STR
                                          + k + (lane >> 4) * 8) * 2;
                ldsm_x4(ah[mf], uAh + off);
                ldsm_x4(al[mf], uAl + off);
            }
            #pragma unroll
            for (int nq = 0; nq < 4; nq++) {
                uint32_t off = (uint32_t)((wn + nq * 16 + (lane & 7) + ((lane >> 4) & 1) * 8)
                                          * SA_STR + k + ((lane >> 3) & 1) * 8) * 2;
                ldsm_x4(bh[nq], uBh + off);
                ldsm_x4(bl[nq], uBl + off);
            }
            #pragma unroll
            for (int t3 = 0; t3 < 3; t3++) {
                uint32_t (*A)[4]  = (t3 == 2) ? al : ah;
                uint32_t (*Bf)[4] = (t3 == 1) ? bl : bh;
                #pragma unroll
                for (int mf = 0; mf < 2; mf++)
                    #pragma unroll
                    for (int nq = 0; nq < 4; nq++) {
                        mma_bf16(d[mf][nq * 2 + 0], A[mf], &Bf[nq][0]);
                        mma_bf16(d[mf][nq * 2 + 1], A[mf], &Bf[nq][2]);
                    }
            }
        }
        __syncthreads();
    }

    float* part = g_part[z];
    #pragma unroll
    for (int mf = 0; mf < 2; mf++) {
        int r = row0 + wm + mf * 16 + (lane >> 2);
        #pragma unroll
        for (int nf = 0; nf < 8; nf++) {
            int c = col0 + wn + nf * 8 + (lane & 3) * 2;
            *reinterpret_cast<float2*>(&part[(size_t)r * ND + c]) =
                make_float2(d[mf][nf][0], d[mf][nf][1]);
            *reinterpret_cast<float2*>(&part[(size_t)(r + 8) * ND + c]) =
                make_float2(d[mf][nf][2], d[mf][nf][3]);
        }
    }
}

// =============================================================================
// Kernel 5: out = p0 + p1 + p2 + bias
// =============================================================================
__global__ void __launch_bounds__(256) reduce_kernel(
    const float* __restrict__ bo, float* __restrict__ out)
{
    int idx = blockIdx.x * 256 + threadIdx.x;
    float4 a = reinterpret_cast<const float4*>(g_part[0])[idx];
    float4 b = reinterpret_cast<const float4*>(g_part[1])[idx];
    float4 c = reinterpret_cast<const float4*>(g_part[2])[idx];
    float4 bb = reinterpret_cast<const float4*>(bo)[idx & 127];
    float4 r;
    r.x = a.x + b.x + c.x + bb.x;
    r.y = a.y + b.y + c.y + bb.y;
    r.z = a.z + b.z + c.z + bb.z;
    r.w = a.w + b.w + c.w + bb.w;
    reinterpret_cast<float4*>(out)[idx] = r;
}

// =============================================================================
extern "C" void kernel_launch(void* const* d_in, const int* in_sizes, int n_in,
                              void* d_out, int out_size)
{
    (void)in_sizes; (void)n_in; (void)out_size;
    const float* queries = (const float*)d_in[0];
    const float* keys    = (const float*)d_in[1];
    const float* values  = (const float*)d_in[2];
    // d_in[3] = attn_mask (all false; no effect on the math)
    const float* Wq = (const float*)d_in[4];
    const float* bq = (const float*)d_in[5];
    const float* Wk = (const float*)d_in[6];
    const float* bk = (const float*)d_in[7];
    const float* Wv = (const float*)d_in[8];
    const float* bv = (const float*)d_in[9];
    const float* core = (const float*)d_in[10];
    const float* Wo = (const float*)d_in[11];
    const float* bo = (const float*)d_in[12];
    float* out = (float*)d_out;

    cudaFuncSetAttribute(stageA_hmma, cudaFuncAttributeMaxDynamicSharedMemorySize, SA_SMEM);
    cudaFuncSetAttribute(stageB_hmma, cudaFuncAttributeMaxDynamicSharedMemorySize, SB_SMEM);

    convWo_kernel<<<dim3(288, 16), 256>>>(Wo);
    proj_kernel<<<dim3(24, 8, 3), 256>>>(queries, keys, values,
                                         Wq, Wk, Wv, bq, bk, bv, core);
    convV_kernel<<<1536, 256>>>();
    stageA_hmma<<<dim3(72, 32), 256, SA_SMEM>>>();
    stageB_hmma<<<dim3(24, 4, 3), 256, SB_SMEM>>>();
    reduce_kernel<<<1536, 256>>>(bo, out);
}